// round 3
// baseline (speedup 1.0000x reference)
#include <cuda_runtime.h>

#define CIN 128
#define C 64
#define H2f 0.01f
#define EB 8
#define NNODES 50000
#define NEDGES 800000

__device__ float g_deg[NNODES];
__device__ float g_W[NEDGES];
__device__ float g_buf[3][(long)NNODES * C];

// ---- helpers: packed f32x2 ----
__device__ __forceinline__ unsigned long long dup2(float x) {
    unsigned long long d;
    asm("mov.b64 %0, {%1, %1};" : "=l"(d) : "f"(x));
    return d;
}
__device__ __forceinline__ void ffma2(unsigned long long& acc,
                                      unsigned long long a, unsigned long long b) {
    asm("fma.rn.f32x2 %0, %1, %2, %0;" : "+l"(acc) : "l"(a), "l"(b));
}
__device__ __forceinline__ float2 u2f2(unsigned long long u) {
    float2 f;
    asm("mov.b64 {%0, %1}, %2;" : "=f"(f.x), "=f"(f.y) : "l"(u));
    return f;
}
__device__ __forceinline__ unsigned long long f2u2(float x, float y) {
    unsigned long long u;
    asm("mov.b64 %0, {%1, %2};" : "=l"(u) : "f"(x), "f"(y));
    return u;
}
__device__ __forceinline__ float tanh_fast(float x) {
    float y;
    asm("tanh.approx.f32 %0, %1;" : "=f"(y) : "f"(x));
    return y;
}

// Fused: proj (blocks [0, nPB)) + zero g_deg (blocks [nPB, ...)).
// proj writes x0 to buf0, buf1, buf2 (buf2 = layer-0 A since 2x0-x0 = x0).
__global__ void __launch_bounds__(256) k_pz(const float* __restrict__ xn,
                                            const float* __restrict__ K1,
                                            int nN, int nPB) {
    if (blockIdx.x >= nPB) {
        int i = (blockIdx.x - nPB) * 256 + threadIdx.x;
        if (i < nN) g_deg[i] = 0.0f;
        return;
    }
    __shared__ float Ks[C * CIN];
    __shared__ float xs[CIN * 64];
    int tid = threadIdx.x;
    for (int i = tid; i < C * CIN; i += 256) Ks[i] = K1[i];
    int n0 = blockIdx.x * 64;
    for (int i = tid; i < CIN * 64; i += 256) {
        int k = i >> 6, nl = i & 63;
        int n = n0 + nl;
        xs[i] = (n < nN) ? xn[(long)k * nN + n] : 0.0f;
    }
    __syncthreads();
    int nl = tid & 63;
    int cb = (tid >> 6) * 16;
    float acc[16];
#pragma unroll
    for (int j = 0; j < 16; j++) acc[j] = 0.0f;
    for (int k = 0; k < CIN; k++) {
        float xv = xs[k * 64 + nl];
#pragma unroll
        for (int j = 0; j < 16; j++) acc[j] = fmaf(Ks[(cb + j) * CIN + k], xv, acc[j]);
    }
    int n = n0 + nl;
    if (n < nN) {
#pragma unroll
        for (int j = 0; j < 16; j++) {
            float v = fmaxf(acc[j], 0.0f);
            g_buf[0][(long)n * C + cb + j] = v;
            g_buf[1][(long)n * C + cb + j] = v;
            g_buf[2][(long)n * C + cb + j] = v;
        }
    }
}

__global__ void k_degree(const int* __restrict__ Jv, int nE) {
    int e = blockIdx.x * blockDim.x + threadIdx.x;
    if (e < nE) atomicAdd(&g_deg[Jv[e]], 1.0f);
}

// W = rsqrt(deg[I]+1) * rsqrt(deg[J]+1)  (self-loop folded as +1)
__global__ void k_Wd(const int* __restrict__ Iv, const int* __restrict__ Jv, int nE) {
    int e = blockIdx.x * blockDim.x + threadIdx.x;
    if (e < nE)
        g_W[e] = rsqrtf(g_deg[Iv[e]] + 1.0f) * rsqrtf(g_deg[Jv[e]] + 1.0f);
}

// A = 2*x_cur - x_old
__global__ void k_init(int curI, int oldI, int nxtI, int n4) {
    int i = blockIdx.x * blockDim.x + threadIdx.x;
    if (i >= n4) return;
    float4 a = ((const float4*)g_buf[curI])[i];
    float4 b = ((const float4*)g_buf[oldI])[i];
    ((float4*)g_buf[nxtI])[i] = make_float4(2.0f * a.x - b.x, 2.0f * a.y - b.y,
                                            2.0f * a.z - b.z, 2.0f * a.w - b.w);
}

// Hot kernel. Warp handles EB=8 edges. GEMVs use fma.rn.f32x2 with acc packed
// over edge pairs; staging reads are broadcast LDS.128 (1 wavefront each).
// Staging layout: sb[c*8 + (e ^ 2*((c>>2)&3))] = val[c][e]  (16B-group-safe swizzle).
__global__ void __launch_bounds__(256, 3) k_edge(int xI, int aI,
        const int* __restrict__ Iv, const int* __restrict__ Jv,
        const float* __restrict__ Km, int nE)
{
    __shared__ float Ktp[C * C];        // Ktp[c*64 + 2L + h] = K[L+32h][c]
    __shared__ float Ktr[C * C];        // Ktr[o*64 + c]      = K[c][o]
    __shared__ float sbuf[8][C * EB];   // per-warp staging
    int tid = threadIdx.x;
    for (int i = tid; i < C * C; i += 256) {
        float v = Km[i];
        int r = i >> 6, q = i & 63;
        Ktp[q * 64 + 2 * (r & 31) + (r >> 5)] = v;
        Ktr[q * 64 + r] = v;
    }
    __syncthreads();
    const float2* x2 = (const float2*)g_buf[xI];
    float* A = g_buf[aI];
    int lane = tid & 31;
    int wid = tid >> 5;
    float* sb = sbuf[wid];
    const float2* Ktp2 = (const float2*)Ktp;
    const float2* Ktr2 = (const float2*)Ktr;
    long gw = (long)blockIdx.x * 8 + wid;
    long nW = (long)gridDim.x * 8;
    int lh = lane & 15;                 // scatter sub-lane
    for (long e0 = gw * EB; e0 < nE; e0 += nW * EB) {
        int ii = 0, jj = 0; float ww = 0.0f;
        if (lane < EB && e0 + lane < (long)nE) {
            ii = Iv[e0 + lane];
            jj = Jv[e0 + lane];
            ww = g_W[e0 + lane];
        }
        // ---- gather: g[c][e] = W*(x_I - x_J); lane owns rows 2L, 2L+1 ----
        {
            int sg = 2 * ((lane >> 1) & 3);   // 2*(((2L)>>2)&3)
#pragma unroll
            for (int e = 0; e < EB; e++) {
                int i = __shfl_sync(0xffffffffu, ii, e);
                int j = __shfl_sync(0xffffffffu, jj, e);
                float w = __shfl_sync(0xffffffffu, ww, e);
                float2 xi = x2[(long)i * 32 + lane];
                float2 xj = x2[(long)j * 32 + lane];
                int col = e ^ sg;
                sb[(2 * lane) * EB + col]      = w * (xi.x - xj.x);
                sb[(2 * lane + 1) * EB + col]  = w * (xi.y - xj.y);
            }
        }
        __syncwarp();
        // ---- GEMM1: t[o][e] = sum_c K[o][c]*g[c][e]; o = lane, lane+32 ----
        unsigned long long acc0[EB / 2], acc1[EB / 2];
#pragma unroll
        for (int p = 0; p < EB / 2; p++) { acc0[p] = 0ull; acc1[p] = 0ull; }
#pragma unroll 4
        for (int c = 0; c < C; c++) {
            float2 kv = Ktp2[c * 32 + lane];
            unsigned long long kx = dup2(kv.x);
            unsigned long long ky = dup2(kv.y);
            int s = (c >> 2) & 3, sl = s & 1, sh = s >> 1;
            const longlong2* gr = (const longlong2*)(sb + c * EB);
#pragma unroll
            for (int k = 0; k < 2; k++) {
                longlong2 v = gr[k ^ sh];          // broadcast LDS.128
                int pA = 2 * k + sl, pB = 2 * k + 1 - sl;
                ffma2(acc0[pA], kx, (unsigned long long)v.x);
                ffma2(acc0[pB], kx, (unsigned long long)v.y);
                ffma2(acc1[pA], ky, (unsigned long long)v.x);
                ffma2(acc1[pB], ky, (unsigned long long)v.y);
            }
        }
        __syncwarp();
        // ---- tanh, store t (pairs as STS.64, same swizzled layout) ----
        {
            int s0 = 2 * ((lane >> 2) & 3);       // swizzle for rows lane, lane+32
#pragma unroll
            for (int p = 0; p < EB / 2; p++) {
                float2 a = u2f2(acc0[p]);
                float2 b = u2f2(acc1[p]);
                int col = (2 * p) ^ s0;
                *(unsigned long long*)(sb + lane * EB + col) =
                    f2u2(tanh_fast(a.x), tanh_fast(a.y));
                *(unsigned long long*)(sb + (lane + 32) * EB + col) =
                    f2u2(tanh_fast(b.x), tanh_fast(b.y));
            }
        }
        __syncwarp();
        // ---- GEMM2: d[c][e] = sum_o K[c][o]*t[o][e]; c = 2L, 2L+1 ----
        unsigned long long d0[EB / 2], d1[EB / 2];
#pragma unroll
        for (int p = 0; p < EB / 2; p++) { d0[p] = 0ull; d1[p] = 0ull; }
#pragma unroll 4
        for (int o = 0; o < C; o++) {
            float2 kv = Ktr2[o * 32 + lane];
            unsigned long long kx = dup2(kv.x);
            unsigned long long ky = dup2(kv.y);
            int s = (o >> 2) & 3, sl = s & 1, sh = s >> 1;
            const longlong2* tr = (const longlong2*)(sb + o * EB);
#pragma unroll
            for (int k = 0; k < 2; k++) {
                longlong2 v = tr[k ^ sh];
                int pA = 2 * k + sl, pB = 2 * k + 1 - sl;
                ffma2(d0[pA], kx, (unsigned long long)v.x);
                ffma2(d0[pB], kx, (unsigned long long)v.y);
                ffma2(d1[pA], ky, (unsigned long long)v.x);
                ffma2(d1[pB], ky, (unsigned long long)v.y);
            }
        }
        __syncwarp();
        // ---- stage d edge-major (conflict-free STS.64): sb[e*64 + c] ----
#pragma unroll
        for (int p = 0; p < EB / 2; p++) {
            float2 da = u2f2(d0[p]);   // c=2L  : edges 2p, 2p+1
            float2 db = u2f2(d1[p]);   // c=2L+1
            *(unsigned long long*)(sb + (2 * p) * C + 2 * lane)     = f2u2(da.x, db.x);
            *(unsigned long long*)(sb + (2 * p + 1) * C + 2 * lane) = f2u2(da.y, db.y);
        }
        __syncwarp();
        // ---- scatter: lanes 0-15 -> I row (neg), 16-31 -> J row (pos) ----
#pragma unroll
        for (int e = 0; e < EB; e++) {
            if (e0 + e < (long)nE) {
                int i = __shfl_sync(0xffffffffu, ii, e);
                int j = __shfl_sync(0xffffffffu, jj, e);
                float w = __shfl_sync(0xffffffffu, ww, e);
                float4 v = ((const float4*)(sb + e * C))[lh];
                float sc = H2f * w;
                if (lane < 16) sc = -sc;
                int node = (lane < 16) ? i : j;
                float* p4 = A + (long)node * C + 4 * lh;
                asm volatile("red.global.add.v4.f32 [%0], {%1, %2, %3, %4};"
                             :: "l"(p4), "f"(sc * v.x), "f"(sc * v.y),
                                "f"(sc * v.z), "f"(sc * v.w) : "memory");
            }
        }
        __syncwarp();
    }
}

// out[n][o] = sum_c KNclose[o][c] * x[n][c]
__global__ void __launch_bounds__(128) k_out(int xIdx, const float* __restrict__ KNc,
                                             float* __restrict__ out, int nN, int nOut) {
    __shared__ float Ks[40 * C];
    for (int i = threadIdx.x; i < nOut * C; i += 128) Ks[i] = KNc[i];
    __syncthreads();
    int n = blockIdx.x * 128 + threadIdx.x;
    if (n >= nN) return;
    const float* xr = g_buf[xIdx] + (long)n * C;
    float xv[C];
#pragma unroll
    for (int q = 0; q < C / 4; q++) {
        float4 v = ((const float4*)xr)[q];
        xv[4 * q] = v.x; xv[4 * q + 1] = v.y; xv[4 * q + 2] = v.z; xv[4 * q + 3] = v.w;
    }
    for (int o = 0; o < nOut; o++) {
        float acc = 0.0f;
#pragma unroll
        for (int c = 0; c < C; c++) acc = fmaf(Ks[o * C + c], xv[c], acc);
        out[(long)n * nOut + o] = acc;
    }
}

extern "C" void kernel_launch(void* const* d_in, const int* in_sizes, int n_in,
                              void* d_out, int out_size) {
    const float* xn = (const float*)d_in[0];
    const int* Iv = (const int*)d_in[1];
    const int* Jv = (const int*)d_in[2];
    int idx = 3;
    if (n_in >= 7 && in_sizes[3] == 1) idx = 4;   // skip scalar n_nodes input
    const float* K1  = (const float*)d_in[idx];
    const float* KN2 = (const float*)d_in[idx + 1];
    const float* KNc = (const float*)d_in[idx + 2];
    int nE = in_sizes[1];
    int nN = in_sizes[0] / CIN;
    int nLayer = in_sizes[idx + 1] / (C * C);
    int nOut = in_sizes[idx + 2] / C;
    float* out = (float*)d_out;

    int nPB = (nN + 63) / 64;
    int nZB = (nN + 255) / 256;
    k_pz<<<nPB + nZB, 256>>>(xn, K1, nN, nPB);            // launch 0
    k_degree<<<(nE + 255) / 256, 256>>>(Jv, nE);          // launch 1
    k_Wd<<<(nE + 255) / 256, 256>>>(Iv, Jv, nE);          // launch 2

    int cur = 0, old = 1, nxt = 2;
    int n4 = nN * C / 4;
    for (int l = 0; l < nLayer; l++) {
        if (l > 0)
            k_init<<<(n4 + 255) / 256, 256>>>(cur, old, nxt, n4);
        k_edge<<<912, 256>>>(cur, nxt, Iv, Jv, KN2 + (long)l * C * C, nE);  // layer0 = launch 3
        int t = old; old = cur; cur = nxt; nxt = t;
    }
    k_out<<<(nN + 127) / 128, 128>>>(cur, KNc, out, nN, nOut);
}

// round 4
// speedup vs baseline: 6.0516x; 6.0516x over previous
#include <cuda_runtime.h>

#define CIN 128
#define C 64
#define H2f 0.01f
#define EB 8
#define NNODES 50000
#define NEDGES 800000

__device__ float g_deg[NNODES];
__device__ float g_W[NEDGES];
__device__ float g_buf[3][(long)NNODES * C];

// ---- helpers: packed f32x2 ----
__device__ __forceinline__ unsigned long long dup2(float x) {
    unsigned long long d;
    asm("mov.b64 %0, {%1, %1};" : "=l"(d) : "f"(x));
    return d;
}
__device__ __forceinline__ void ffma2(unsigned long long& acc,
                                      unsigned long long a, unsigned long long b) {
    asm("fma.rn.f32x2 %0, %1, %2, %0;" : "+l"(acc) : "l"(a), "l"(b));
}
__device__ __forceinline__ float2 u2f2(unsigned long long u) {
    float2 f;
    asm("mov.b64 {%0, %1}, %2;" : "=f"(f.x), "=f"(f.y) : "l"(u));
    return f;
}
__device__ __forceinline__ unsigned long long f2u2(float x, float y) {
    unsigned long long u;
    asm("mov.b64 %0, {%1, %2};" : "=l"(u) : "f"(x), "f"(y));
    return u;
}
__device__ __forceinline__ float tanh_fast(float x) {
    float y;
    asm("tanh.approx.f32 %0, %1;" : "=f"(y) : "f"(x));
    return y;
}

// Fused: proj (blocks [0, nPB)) + zero g_deg (blocks [nPB, ...)).
// proj writes x0 to buf0, buf1, buf2 (buf2 = layer-0 A since 2x0-x0 = x0).
__global__ void __launch_bounds__(256) k_pz(const float* __restrict__ xn,
                                            const float* __restrict__ K1,
                                            int nN, int nPB) {
    if (blockIdx.x >= nPB) {
        int i = (blockIdx.x - nPB) * 256 + threadIdx.x;
        if (i < nN) g_deg[i] = 0.0f;
        return;
    }
    __shared__ float Ks[C * CIN];
    __shared__ float xs[CIN * 64];
    int tid = threadIdx.x;
    for (int i = tid; i < C * CIN; i += 256) Ks[i] = K1[i];
    int n0 = blockIdx.x * 64;
    for (int i = tid; i < CIN * 64; i += 256) {
        int k = i >> 6, nl = i & 63;
        int n = n0 + nl;
        xs[i] = (n < nN) ? xn[(long)k * nN + n] : 0.0f;
    }
    __syncthreads();
    int nl = tid & 63;
    int cb = (tid >> 6) * 16;
    float acc[16];
#pragma unroll
    for (int j = 0; j < 16; j++) acc[j] = 0.0f;
    for (int k = 0; k < CIN; k++) {
        float xv = xs[k * 64 + nl];
#pragma unroll
        for (int j = 0; j < 16; j++) acc[j] = fmaf(Ks[(cb + j) * CIN + k], xv, acc[j]);
    }
    int n = n0 + nl;
    if (n < nN) {
#pragma unroll
        for (int j = 0; j < 16; j++) {
            float v = fmaxf(acc[j], 0.0f);
            g_buf[0][(long)n * C + cb + j] = v;
            g_buf[1][(long)n * C + cb + j] = v;
            g_buf[2][(long)n * C + cb + j] = v;
        }
    }
}

__global__ void k_degree(const int* __restrict__ Jv, int nE) {
    int e = blockIdx.x * blockDim.x + threadIdx.x;
    if (e < nE) atomicAdd(&g_deg[Jv[e]], 1.0f);
}

// W = rsqrt(deg[I]+1) * rsqrt(deg[J]+1)  (self-loop folded as +1)
__global__ void k_Wd(const int* __restrict__ Iv, const int* __restrict__ Jv, int nE) {
    int e = blockIdx.x * blockDim.x + threadIdx.x;
    if (e < nE)
        g_W[e] = rsqrtf(g_deg[Iv[e]] + 1.0f) * rsqrtf(g_deg[Jv[e]] + 1.0f);
}

// A = 2*x_cur - x_old
__global__ void k_init(int curI, int oldI, int nxtI, int n4) {
    int i = blockIdx.x * blockDim.x + threadIdx.x;
    if (i >= n4) return;
    float4 a = ((const float4*)g_buf[curI])[i];
    float4 b = ((const float4*)g_buf[oldI])[i];
    ((float4*)g_buf[nxtI])[i] = make_float4(2.0f * a.x - b.x, 2.0f * a.y - b.y,
                                            2.0f * a.z - b.z, 2.0f * a.w - b.w);
}

// One GEMV step for 16 consecutive k-rows with COMPILE-TIME swizzle constants.
// kk: base row (multiple of 16). acc index constants fold because s = (c4>>2)&3.
#define GEMV16(Kp2, buf, A0, A1, KK)                                          \
    _Pragma("unroll")                                                         \
    for (int c4 = 0; c4 < 16; c4++) {                                         \
        const int c_ = (KK) + c4;                                             \
        const int s_ = (c4 >> 2) & 3, sl_ = s_ & 1, sh_ = s_ >> 1;            \
        float2 kv = (Kp2)[c_ * 32 + lane];                                    \
        unsigned long long kx = dup2(kv.x);                                   \
        unsigned long long ky = dup2(kv.y);                                   \
        const longlong2* vr = (const longlong2*)((buf) + c_ * EB);            \
        _Pragma("unroll")                                                     \
        for (int k_ = 0; k_ < 2; k_++) {                                      \
            longlong2 v = vr[k_ ^ sh_];                                       \
            ffma2(A0[2 * k_ + sl_], kx, (unsigned long long)v.x);             \
            ffma2(A0[2 * k_ + 1 - sl_], kx, (unsigned long long)v.y);         \
            ffma2(A1[2 * k_ + sl_], ky, (unsigned long long)v.x);             \
            ffma2(A1[2 * k_ + 1 - sl_], ky, (unsigned long long)v.y);         \
        }                                                                     \
    }

// Hot kernel. Warp handles EB=8 edges. GEMVs use fma.rn.f32x2 with acc packed
// over edge pairs; staging reads are broadcast LDS.128 (1 wavefront each).
// Staging layout: sb[c*8 + (e ^ 2*((c>>2)&3))] = val[c][e].
__global__ void __launch_bounds__(256, 3) k_edge(int xI, int aI,
        const int* __restrict__ Iv, const int* __restrict__ Jv,
        const float* __restrict__ Km, int nE)
{
    __shared__ float Ktp[C * C];        // Ktp[c*64 + 2L + h] = K[L+32h][c]
    __shared__ float Ktr[C * C];        // Ktr[o*64 + c]      = K[c][o]
    __shared__ float sbuf[8][C * EB];   // per-warp staging
    int tid = threadIdx.x;
    for (int i = tid; i < C * C; i += 256) {
        float v = Km[i];
        int r = i >> 6, q = i & 63;
        Ktp[q * 64 + 2 * (r & 31) + (r >> 5)] = v;
        Ktr[q * 64 + r] = v;
    }
    __syncthreads();
    const float2* x2 = (const float2*)g_buf[xI];
    float* A = g_buf[aI];
    int lane = tid & 31;
    int wid = tid >> 5;
    float* sb = sbuf[wid];
    const float2* Ktp2 = (const float2*)Ktp;
    const float2* Ktr2 = (const float2*)Ktr;
    long gw = (long)blockIdx.x * 8 + wid;
    long nW = (long)gridDim.x * 8;
    int lh = lane & 15;                 // scatter sub-lane
    for (long e0 = gw * EB; e0 < nE; e0 += nW * EB) {
        int ii = 0, jj = 0; float ww = 0.0f;
        if (lane < EB && e0 + lane < (long)nE) {
            ii = Iv[e0 + lane];
            jj = Jv[e0 + lane];
            ww = g_W[e0 + lane];
        }
        // ---- gather: g[c][e] = W*(x_I - x_J); lane owns rows 2L, 2L+1 ----
        {
            int sg = 2 * ((lane >> 1) & 3);   // 2*(((2L)>>2)&3)
#pragma unroll
            for (int e = 0; e < EB; e++) {
                int i = __shfl_sync(0xffffffffu, ii, e);
                int j = __shfl_sync(0xffffffffu, jj, e);
                float w = __shfl_sync(0xffffffffu, ww, e);
                float2 xi = x2[(long)i * 32 + lane];
                float2 xj = x2[(long)j * 32 + lane];
                int col = e ^ sg;
                sb[(2 * lane) * EB + col]      = w * (xi.x - xj.x);
                sb[(2 * lane + 1) * EB + col]  = w * (xi.y - xj.y);
            }
        }
        __syncwarp();
        // ---- GEMM1: t[o][e] = sum_c K[o][c]*g[c][e]; o = lane, lane+32 ----
        unsigned long long acc0[EB / 2], acc1[EB / 2];
#pragma unroll
        for (int p = 0; p < EB / 2; p++) { acc0[p] = 0ull; acc1[p] = 0ull; }
#pragma unroll
        for (int cc = 0; cc < C; cc += 16) {
            GEMV16(Ktp2, sb, acc0, acc1, cc)
        }
        __syncwarp();
        // ---- tanh, store t (pairs as STS.64, same swizzled layout) ----
        {
            int s0 = 2 * ((lane >> 2) & 3);   // swizzle for rows lane, lane+32
#pragma unroll
            for (int p = 0; p < EB / 2; p++) {
                float2 a = u2f2(acc0[p]);
                float2 b = u2f2(acc1[p]);
                int col = (2 * p) ^ s0;
                *(unsigned long long*)(sb + lane * EB + col) =
                    f2u2(tanh_fast(a.x), tanh_fast(a.y));
                *(unsigned long long*)(sb + (lane + 32) * EB + col) =
                    f2u2(tanh_fast(b.x), tanh_fast(b.y));
            }
        }
        __syncwarp();
        // ---- GEMM2: d[c][e] = sum_o K[c][o]*t[o][e]; c = 2L, 2L+1 ----
        unsigned long long d0[EB / 2], d1[EB / 2];
#pragma unroll
        for (int p = 0; p < EB / 2; p++) { d0[p] = 0ull; d1[p] = 0ull; }
#pragma unroll
        for (int oo = 0; oo < C; oo += 16) {
            GEMV16(Ktr2, sb, d0, d1, oo)
        }
        __syncwarp();
        // ---- stage d edge-major (conflict-free STS.64): sb[e*64 + c] ----
#pragma unroll
        for (int p = 0; p < EB / 2; p++) {
            float2 da = u2f2(d0[p]);   // c=2L  : edges 2p, 2p+1
            float2 db = u2f2(d1[p]);   // c=2L+1
            *(unsigned long long*)(sb + (2 * p) * C + 2 * lane)     = f2u2(da.x, db.x);
            *(unsigned long long*)(sb + (2 * p + 1) * C + 2 * lane) = f2u2(da.y, db.y);
        }
        __syncwarp();
        // ---- scatter: lanes 0-15 -> I row (neg), 16-31 -> J row (pos) ----
#pragma unroll
        for (int e = 0; e < EB; e++) {
            if (e0 + e < (long)nE) {
                int i = __shfl_sync(0xffffffffu, ii, e);
                int j = __shfl_sync(0xffffffffu, jj, e);
                float w = __shfl_sync(0xffffffffu, ww, e);
                float4 v = ((const float4*)(sb + e * C))[lh];
                float sc = H2f * w;
                if (lane < 16) sc = -sc;
                int node = (lane < 16) ? i : j;
                float* p4 = A + (long)node * C + 4 * lh;
                asm volatile("red.global.add.v4.f32 [%0], {%1, %2, %3, %4};"
                             :: "l"(p4), "f"(sc * v.x), "f"(sc * v.y),
                                "f"(sc * v.z), "f"(sc * v.w) : "memory");
            }
        }
        __syncwarp();
    }
}

// out[n][o] = sum_c KNclose[o][c] * x[n][c]
__global__ void __launch_bounds__(128) k_out(int xIdx, const float* __restrict__ KNc,
                                             float* __restrict__ out, int nN, int nOut) {
    __shared__ float Ks[40 * C];
    for (int i = threadIdx.x; i < nOut * C; i += 128) Ks[i] = KNc[i];
    __syncthreads();
    int n = blockIdx.x * 128 + threadIdx.x;
    if (n >= nN) return;
    const float* xr = g_buf[xIdx] + (long)n * C;
    float xv[C];
#pragma unroll
    for (int q = 0; q < C / 4; q++) {
        float4 v = ((const float4*)xr)[q];
        xv[4 * q] = v.x; xv[4 * q + 1] = v.y; xv[4 * q + 2] = v.z; xv[4 * q + 3] = v.w;
    }
    for (int o = 0; o < nOut; o++) {
        float acc = 0.0f;
#pragma unroll
        for (int c = 0; c < C; c++) acc = fmaf(Ks[o * C + c], xv[c], acc);
        out[(long)n * nOut + o] = acc;
    }
}

extern "C" void kernel_launch(void* const* d_in, const int* in_sizes, int n_in,
                              void* d_out, int out_size) {
    const float* xn = (const float*)d_in[0];
    const int* Iv = (const int*)d_in[1];
    const int* Jv = (const int*)d_in[2];
    int idx = 3;
    if (n_in >= 7 && in_sizes[3] == 1) idx = 4;   // skip scalar n_nodes input
    const float* K1  = (const float*)d_in[idx];
    const float* KN2 = (const float*)d_in[idx + 1];
    const float* KNc = (const float*)d_in[idx + 2];
    int nE = in_sizes[1];
    int nN = in_sizes[0] / CIN;
    int nLayer = in_sizes[idx + 1] / (C * C);
    int nOut = in_sizes[idx + 2] / C;
    float* out = (float*)d_out;

    int nPB = (nN + 63) / 64;
    int nZB = (nN + 255) / 256;
    k_pz<<<nPB + nZB, 256>>>(xn, K1, nN, nPB);            // launch 0
    k_degree<<<(nE + 255) / 256, 256>>>(Jv, nE);          // launch 1
    k_Wd<<<(nE + 255) / 256, 256>>>(Iv, Jv, nE);          // launch 2

    int cur = 0, old = 1, nxt = 2;
    int n4 = nN * C / 4;
    for (int l = 0; l < nLayer; l++) {
        if (l > 0)
            k_init<<<(n4 + 255) / 256, 256>>>(cur, old, nxt, n4);
        k_edge<<<912, 256>>>(cur, nxt, Iv, Jv, KN2 + (long)l * C * C, nE);  // layer1 = launch 5
        int t = old; old = cur; cur = nxt; nxt = t;
    }
    k_out<<<(nN + 127) / 128, 128>>>(cur, KNc, out, nN, nOut);
}